// round 1
// baseline (speedup 1.0000x reference)
#include <cuda_runtime.h>
#include <mma.h>
#include <cstdint>

using namespace nvcuda;

#define B_    8
#define L_    512
#define H_    12
#define D_    64
#define HID   768
#define OUTD  1536
#define MROWS 4096          // B_*L_
#define BHN   96            // B_*H_

// Scratch (device globals — no runtime allocation allowed)
__device__ float g_x[MROWS * OUTD];       // projection output (pre-RoPE)
__device__ float g_q[BHN * L_ * D_];      // q, laid out (bh, l, d)
__device__ float g_k[BHN * L_ * D_];      // k, laid out (bh, l, d)

// ---------------------------------------------------------------------------
// Kernel 1: x = inputs @ W   (bias deferred to RoPE kernel)
// 3xTF32 (hi/lo split) for ~fp32 accuracy on tensor cores.
// Block tile 64x64, BK=32, 4 warps (2x2), each warp 32x32 via 2x2 m16n16k8.
// ---------------------------------------------------------------------------
__global__ __launch_bounds__(128) void gemm1_kernel(const float* __restrict__ A,
                                                    const float* __restrict__ W) {
    __shared__ float As_hi[64][36];
    __shared__ float As_lo[64][36];
    __shared__ float Bs_hi[32][68];
    __shared__ float Bs_lo[32][68];

    const int m0  = blockIdx.y * 64;
    const int n0  = blockIdx.x * 64;
    const int tid = threadIdx.x;
    const int warp = tid >> 5;
    const int wr = warp >> 1;    // 0..1: warp row
    const int wc = warp & 1;     // 0..1: warp col

    wmma::fragment<wmma::accumulator, 16, 16, 8, float> acc[2][2];
    #pragma unroll
    for (int i = 0; i < 2; i++)
        #pragma unroll
        for (int j = 0; j < 2; j++)
            wmma::fill_fragment(acc[i][j], 0.0f);

    for (int k0 = 0; k0 < HID; k0 += 32) {
        // Load A tile 64x32 (512 float4, 4 per thread), split into tf32 hi/lo
        #pragma unroll
        for (int it = 0; it < 4; it++) {
            int idx = tid + it * 128;           // 0..511
            int r = idx >> 3;                   // 8 float4 per row
            int c = (idx & 7) << 2;
            float4 v = *reinterpret_cast<const float4*>(
                &A[(size_t)(m0 + r) * HID + k0 + c]);
            float hx = wmma::__float_to_tf32(v.x);
            float hy = wmma::__float_to_tf32(v.y);
            float hz = wmma::__float_to_tf32(v.z);
            float hw = wmma::__float_to_tf32(v.w);
            As_hi[r][c+0] = hx; As_lo[r][c+0] = wmma::__float_to_tf32(v.x - hx);
            As_hi[r][c+1] = hy; As_lo[r][c+1] = wmma::__float_to_tf32(v.y - hy);
            As_hi[r][c+2] = hz; As_lo[r][c+2] = wmma::__float_to_tf32(v.z - hz);
            As_hi[r][c+3] = hw; As_lo[r][c+3] = wmma::__float_to_tf32(v.w - hw);
        }
        // Load B tile 32x64 (512 float4, 4 per thread)
        #pragma unroll
        for (int it = 0; it < 4; it++) {
            int idx = tid + it * 128;
            int r = idx >> 4;                   // 16 float4 per row
            int c = (idx & 15) << 2;
            float4 v = *reinterpret_cast<const float4*>(
                &W[(size_t)(k0 + r) * OUTD + n0 + c]);
            float hx = wmma::__float_to_tf32(v.x);
            float hy = wmma::__float_to_tf32(v.y);
            float hz = wmma::__float_to_tf32(v.z);
            float hw = wmma::__float_to_tf32(v.w);
            Bs_hi[r][c+0] = hx; Bs_lo[r][c+0] = wmma::__float_to_tf32(v.x - hx);
            Bs_hi[r][c+1] = hy; Bs_lo[r][c+1] = wmma::__float_to_tf32(v.y - hy);
            Bs_hi[r][c+2] = hz; Bs_lo[r][c+2] = wmma::__float_to_tf32(v.z - hz);
            Bs_hi[r][c+3] = hw; Bs_lo[r][c+3] = wmma::__float_to_tf32(v.w - hw);
        }
        __syncthreads();

        #pragma unroll
        for (int kk = 0; kk < 32; kk += 8) {
            wmma::fragment<wmma::matrix_a,16,16,8,wmma::precision::tf32,wmma::row_major> ah[2], al[2];
            wmma::fragment<wmma::matrix_b,16,16,8,wmma::precision::tf32,wmma::row_major> bh[2], bl[2];
            #pragma unroll
            for (int i = 0; i < 2; i++) {
                wmma::load_matrix_sync(ah[i], &As_hi[wr*32 + i*16][kk], 36);
                wmma::load_matrix_sync(al[i], &As_lo[wr*32 + i*16][kk], 36);
            }
            #pragma unroll
            for (int j = 0; j < 2; j++) {
                wmma::load_matrix_sync(bh[j], &Bs_hi[kk][wc*32 + j*16], 68);
                wmma::load_matrix_sync(bl[j], &Bs_lo[kk][wc*32 + j*16], 68);
            }
            #pragma unroll
            for (int i = 0; i < 2; i++)
                #pragma unroll
                for (int j = 0; j < 2; j++) {
                    wmma::mma_sync(acc[i][j], ah[i], bh[j], acc[i][j]);
                    wmma::mma_sync(acc[i][j], ah[i], bl[j], acc[i][j]);
                    wmma::mma_sync(acc[i][j], al[i], bh[j], acc[i][j]);
                }
        }
        __syncthreads();
    }

    #pragma unroll
    for (int i = 0; i < 2; i++)
        #pragma unroll
        for (int j = 0; j < 2; j++)
            wmma::store_matrix_sync(
                &g_x[(size_t)(m0 + wr*32 + i*16) * OUTD + n0 + wc*32 + j*16],
                acc[i][j], OUTD, wmma::mem_row_major);
}

// ---------------------------------------------------------------------------
// Kernel 2: bias + RoPE, reshuffle to (bh, l, d)
// One thread per (b, l, h, pair i): handles q and k pair.
// ---------------------------------------------------------------------------
__global__ __launch_bounds__(256) void rope_kernel(const float* __restrict__ bias) {
    int p = blockIdx.x * 256 + threadIdx.x;   // grid sized exactly
    int i    = p & 31;
    int rest = p >> 5;
    int h    = rest % H_;
    int bl   = rest / H_;                     // b*512 + l, 0..4095
    int l    = bl & (L_ - 1);

    const float* xr = &g_x[(size_t)bl * OUTD + h * 128];
    const float* br = &bias[h * 128];
    float q1 = xr[2*i]      + br[2*i];
    float q2 = xr[2*i + 1]  + br[2*i + 1];
    float k1 = xr[64 + 2*i]     + br[64 + 2*i];
    float k2 = xr[64 + 2*i + 1] + br[64 + 2*i + 1];

    // inv_freq = 10000^(-i/32) = exp2(-i * log2(10000)/32)
    float invf = exp2f((float)i * -0.41524101186092027f);
    float th = (float)l * invf;
    float s, c;
    sincosf(th, &s, &c);

    int bh = (bl >> 9) * H_ + h;              // b*12 + h
    float* qo = &g_q[((size_t)bh * L_ + l) * D_];
    float* ko = &g_k[((size_t)bh * L_ + l) * D_];
    qo[2*i]     = q1 * c - q2 * s;
    qo[2*i + 1] = q1 * s + q2 * c;
    ko[2*i]     = k1 * c - k2 * s;
    ko[2*i + 1] = k1 * s + k2 * c;
}

// ---------------------------------------------------------------------------
// Kernel 3: logits[bh] = (q @ k^T) / 8, causal + padding mask.
// 64x64 output tiles; tiles strictly below block diagonal write -FLT_MAX only.
// TF32 wmma, B operand = k^T via col_major matrix_b.
// ---------------------------------------------------------------------------
__global__ __launch_bounds__(128) void attn_kernel(const int* __restrict__ am,
                                                   float* __restrict__ out) {
    const int bh = blockIdx.z;
    const int b  = bh / H_;
    const int tm = blockIdx.y, tn = blockIdx.x;
    const int m0 = tm * 64, n0 = tn * 64;
    float* obase = out + (size_t)bh * L_ * L_;
    const float NEG = __int_as_float(0xFF7FFFFF);  // -FLT_MAX == finfo(f32).min
    const int tid = threadIdx.x;

    if (tm > tn) {   // whole tile causally masked
        float4 negv = make_float4(NEG, NEG, NEG, NEG);
        #pragma unroll
        for (int it = 0; it < 8; it++) {
            int idx = tid + it * 128;          // 0..1023
            int r = idx >> 4;
            int c = (idx & 15) << 2;
            *reinterpret_cast<float4*>(&obase[(size_t)(m0 + r) * L_ + n0 + c]) = negv;
        }
        return;
    }

    __shared__ float qs[64][68];
    __shared__ float ks[64][68];
    const float* qb = &g_q[(size_t)bh * L_ * D_];
    const float* kb = &g_k[(size_t)bh * L_ * D_];

    #pragma unroll
    for (int it = 0; it < 8; it++) {
        int idx = tid + it * 128;
        int r = idx >> 4;
        int c = (idx & 15) << 2;
        float4 v = *reinterpret_cast<const float4*>(&qb[(size_t)(m0 + r) * D_ + c]);
        qs[r][c+0] = wmma::__float_to_tf32(v.x);
        qs[r][c+1] = wmma::__float_to_tf32(v.y);
        qs[r][c+2] = wmma::__float_to_tf32(v.z);
        qs[r][c+3] = wmma::__float_to_tf32(v.w);
        float4 u = *reinterpret_cast<const float4*>(&kb[(size_t)(n0 + r) * D_ + c]);
        ks[r][c+0] = wmma::__float_to_tf32(u.x);
        ks[r][c+1] = wmma::__float_to_tf32(u.y);
        ks[r][c+2] = wmma::__float_to_tf32(u.z);
        ks[r][c+3] = wmma::__float_to_tf32(u.w);
    }
    __syncthreads();

    const int warp = tid >> 5;
    const int wr = warp >> 1;
    const int wc = warp & 1;

    wmma::fragment<wmma::accumulator, 16, 16, 8, float> acc[2][2];
    #pragma unroll
    for (int i = 0; i < 2; i++)
        #pragma unroll
        for (int j = 0; j < 2; j++)
            wmma::fill_fragment(acc[i][j], 0.0f);

    #pragma unroll
    for (int kk = 0; kk < D_; kk += 8) {
        wmma::fragment<wmma::matrix_a,16,16,8,wmma::precision::tf32,wmma::row_major> af[2];
        wmma::fragment<wmma::matrix_b,16,16,8,wmma::precision::tf32,wmma::col_major> bf[2];
        #pragma unroll
        for (int i = 0; i < 2; i++)
            wmma::load_matrix_sync(af[i], &qs[wr*32 + i*16][kk], 68);
        #pragma unroll
        for (int j = 0; j < 2; j++)
            wmma::load_matrix_sync(bf[j], &ks[wc*32 + j*16][kk], 68);
        #pragma unroll
        for (int i = 0; i < 2; i++)
            #pragma unroll
            for (int j = 0; j < 2; j++)
                wmma::mma_sync(acc[i][j], af[i], bf[j], acc[i][j]);
    }

    // Stage result through qs (no longer needed), then masked write.
    __syncthreads();
    #pragma unroll
    for (int i = 0; i < 2; i++)
        #pragma unroll
        for (int j = 0; j < 2; j++)
            wmma::store_matrix_sync(&qs[wr*32 + i*16][wc*32 + j*16],
                                    acc[i][j], 68, wmma::mem_row_major);
    __syncthreads();

    const int* amb = am + b * L_;
    #pragma unroll
    for (int it = 0; it < 32; it++) {
        int idx = tid + it * 128;              // 0..4095
        int r = idx >> 6;
        int c = idx & 63;
        int m = m0 + r, n = n0 + c;
        float v = qs[r][c] * 0.125f;
        bool ok = (m <= n) && (amb[m] != 0) && (amb[n] != 0);
        obase[(size_t)m * L_ + n] = ok ? v : NEG;
    }
}

// ---------------------------------------------------------------------------
extern "C" void kernel_launch(void* const* d_in, const int* in_sizes, int n_in,
                              void* d_out, int out_size) {
    const float* inputs = (const float*)d_in[0];
    const float* W      = (const float*)d_in[1];
    const float* bias   = (const float*)d_in[2];
    const int*   am     = (const int*)d_in[3];
    float* out = (float*)d_out;

    gemm1_kernel<<<dim3(OUTD / 64, MROWS / 64), 128>>>(inputs, W);
    rope_kernel<<<(MROWS * H_ * 32) / 256, 256>>>(bias);
    attn_kernel<<<dim3(L_ / 64, L_ / 64, BHN), 128>>>(am, out);
}

// round 2
// speedup vs baseline: 4.3405x; 4.3405x over previous
#include <cuda_runtime.h>
#include <cuda_bf16.h>
#include <mma.h>
#include <cstdint>

using namespace nvcuda;

#define B_    8
#define L_    512
#define H_    12
#define D_    64
#define HID   768
#define OUTD  1536
#define MROWS 4096          // B_*L_
#define BHN   96            // B_*H_

#define NA2   (MROWS * HID / 2)     // 1572864 bf16x2 units
#define NW2   (HID * OUTD / 2)      //  589824
#define NROPE (L_ * 32)             //   16384

// Scratch (device globals — no runtime allocation allowed)
__device__ __nv_bfloat162 g_abf2[NA2];          // inputs in bf16
__device__ __nv_bfloat162 g_wbf2[NW2];          // W in bf16
__device__ __nv_bfloat16  g_q[BHN * L_ * D_];   // q, (bh, l, d) bf16
__device__ __nv_bfloat16  g_k[BHN * L_ * D_];   // k, (bh, l, d) bf16
__device__ float          g_sin[NROPE];
__device__ float          g_cos[NROPE];

// ---------------------------------------------------------------------------
// Kernel 0: convert inputs/W to bf16 + build RoPE tables.
// ---------------------------------------------------------------------------
__global__ __launch_bounds__(256) void prep_kernel(const float* __restrict__ A,
                                                   const float* __restrict__ W) {
    int idx = blockIdx.x * 256 + threadIdx.x;
    if (idx < NA2) {
        float2 v = reinterpret_cast<const float2*>(A)[idx];
        g_abf2[idx] = __floats2bfloat162_rn(v.x, v.y);
    } else if (idx < NA2 + NW2) {
        float2 v = reinterpret_cast<const float2*>(W)[idx - NA2];
        g_wbf2[idx - NA2] = __floats2bfloat162_rn(v.x, v.y);
    } else if (idx < NA2 + NW2 + NROPE) {
        int t = idx - NA2 - NW2;
        int l = t >> 5;
        int i = t & 31;
        // inv_freq = 10000^(-i/32) = exp2(-i * log2(10000)/32)
        float invf = exp2f((float)i * -0.41524101186092027f);
        float th = (float)l * invf;
        float s, c;
        sincosf(th, &s, &c);
        g_sin[t] = s;
        g_cos[t] = c;
    }
}

// ---------------------------------------------------------------------------
// Kernel 1: x = inputs @ W (bf16 wmma), fused bias + RoPE epilogue.
// Block tile 128x128 (one head's q|k columns), BK=64, 8 warps (4x2).
// Epilogue stages fp32 acc through smem (reused) in two 64-row passes,
// applies bias + RoPE, writes bf16 q/k in (bh,l,d) layout.
// ---------------------------------------------------------------------------
__global__ __launch_bounds__(256) void gemm1_kernel(const float* __restrict__ bias) {
    __shared__ __align__(16) unsigned char smem_raw[40960];
    __nv_bfloat16 (*As)[80]  = reinterpret_cast<__nv_bfloat16 (*)[80]>(smem_raw);          // 128x80x2 = 20480
    __nv_bfloat16 (*Bs)[136] = reinterpret_cast<__nv_bfloat16 (*)[136]>(smem_raw + 20480); //  64x136x2 = 17408
    float (*Es)[132]         = reinterpret_cast<float (*)[132]>(smem_raw);                 //  64x132x4 = 33792

    const __nv_bfloat16* Abf = reinterpret_cast<const __nv_bfloat16*>(g_abf2);
    const __nv_bfloat16* Wbf = reinterpret_cast<const __nv_bfloat16*>(g_wbf2);

    const int h   = blockIdx.x;          // head index (n0 = h*128)
    const int m0  = blockIdx.y * 128;
    const int n0  = h * 128;
    const int tid = threadIdx.x;
    const int warp = tid >> 5;
    const int wm = warp >> 1;            // 0..3
    const int wn = warp & 1;             // 0..1

    wmma::fragment<wmma::accumulator, 16, 16, 16, float> acc[2][4];
    #pragma unroll
    for (int i = 0; i < 2; i++)
        #pragma unroll
        for (int j = 0; j < 4; j++)
            wmma::fill_fragment(acc[i][j], 0.0f);

    for (int k0 = 0; k0 < HID; k0 += 64) {
        // A tile 128x64 bf16: 4 x uint4 per thread
        #pragma unroll
        for (int it = 0; it < 4; it++) {
            int idx = tid + it * 256;            // 0..1023
            int r = idx >> 3;                    // 8 uint4 per row
            int c = (idx & 7) << 3;
            *reinterpret_cast<uint4*>(&As[r][c]) =
                *reinterpret_cast<const uint4*>(&Abf[(size_t)(m0 + r) * HID + k0 + c]);
        }
        // B tile 64x128 bf16: 4 x uint4 per thread
        #pragma unroll
        for (int it = 0; it < 4; it++) {
            int idx = tid + it * 256;
            int r = idx >> 4;                    // 16 uint4 per row
            int c = (idx & 15) << 3;
            *reinterpret_cast<uint4*>(&Bs[r][c]) =
                *reinterpret_cast<const uint4*>(&Wbf[(size_t)(k0 + r) * OUTD + n0 + c]);
        }
        __syncthreads();

        #pragma unroll
        for (int kk = 0; kk < 64; kk += 16) {
            wmma::fragment<wmma::matrix_a,16,16,16,__nv_bfloat16,wmma::row_major> af[2];
            wmma::fragment<wmma::matrix_b,16,16,16,__nv_bfloat16,wmma::row_major> bf[4];
            #pragma unroll
            for (int i = 0; i < 2; i++)
                wmma::load_matrix_sync(af[i], &As[wm*32 + i*16][kk], 80);
            #pragma unroll
            for (int j = 0; j < 4; j++)
                wmma::load_matrix_sync(bf[j], &Bs[kk][wn*64 + j*16], 136);
            #pragma unroll
            for (int i = 0; i < 2; i++)
                #pragma unroll
                for (int j = 0; j < 4; j++)
                    wmma::mma_sync(acc[i][j], af[i], bf[j], acc[i][j]);
        }
        __syncthreads();
    }

    // Epilogue: two 64-row passes through Es (aliases operand smem).
    #pragma unroll
    for (int half = 0; half < 2; half++) {
        __syncthreads();
        if ((wm >> 1) == half) {
            #pragma unroll
            for (int i = 0; i < 2; i++)
                #pragma unroll
                for (int j = 0; j < 4; j++)
                    wmma::store_matrix_sync(&Es[(wm & 1)*32 + i*16][wn*64 + j*16],
                                            acc[i][j], 132, wmma::mem_row_major);
        }
        __syncthreads();

        // 64 rows x 64 col-pairs = 4096 pair units / 256 threads = 16 each
        #pragma unroll
        for (int it = 0; it < 16; it++) {
            int idx = tid + it * 256;            // 0..4095
            int r   = idx >> 6;                  // row in half
            int col = (idx & 63) << 1;           // even col 0..126
            int m = m0 + half * 64 + r;
            int l = m & (L_ - 1);
            float x1 = Es[r][col]     + __ldg(&bias[n0 + col]);
            float x2 = Es[r][col + 1] + __ldg(&bias[n0 + col + 1]);
            int i = (col & 63) >> 1;             // pair index within q or k
            float s = g_sin[l * 32 + i];
            float c = g_cos[l * 32 + i];
            float o1 = x1 * c - x2 * s;
            float o2 = x1 * s + x2 * c;
            int bh = (m >> 9) * H_ + h;
            __nv_bfloat16* dst = (col < 64) ? g_q : g_k;
            int d = col & 63;                    // even
            *reinterpret_cast<__nv_bfloat162*>(&dst[((size_t)bh * L_ + l) * D_ + d]) =
                __floats2bfloat162_rn(o1, o2);
        }
    }
}

// ---------------------------------------------------------------------------
// Kernel 2: logits[bh] = (q @ k^T) / 8, causal + padding mask. bf16 wmma.
// 64x64 output tiles; tiles strictly below block diagonal write -FLT_MAX only.
// ---------------------------------------------------------------------------
__global__ __launch_bounds__(128) void attn_kernel(const int* __restrict__ am,
                                                   float* __restrict__ out) {
    const int bh = blockIdx.z;
    const int b  = bh / H_;
    const int tm = blockIdx.y, tn = blockIdx.x;
    const int m0 = tm * 64, n0 = tn * 64;
    float* obase = out + (size_t)bh * L_ * L_;
    const float NEG = __int_as_float(0xFF7FFFFF);  // -FLT_MAX == finfo(f32).min
    const int tid = threadIdx.x;

    if (tm > tn) {   // whole tile causally masked
        float4 negv = make_float4(NEG, NEG, NEG, NEG);
        #pragma unroll
        for (int it = 0; it < 8; it++) {
            int idx = tid + it * 128;          // 0..1023
            int r = idx >> 4;
            int c = (idx & 15) << 2;
            *reinterpret_cast<float4*>(&obase[(size_t)(m0 + r) * L_ + n0 + c]) = negv;
        }
        return;
    }

    __shared__ __align__(16) unsigned char smem_raw[20480];
    __nv_bfloat16 (*qs)[80] = reinterpret_cast<__nv_bfloat16 (*)[80]>(smem_raw);           // 64x80x2 = 10240
    __nv_bfloat16 (*ks)[80] = reinterpret_cast<__nv_bfloat16 (*)[80]>(smem_raw + 10240);
    float (*Es)[68]         = reinterpret_cast<float (*)[68]>(smem_raw);                   // 64x68x4 = 17408

    const __nv_bfloat16* qb = &g_q[(size_t)bh * L_ * D_];
    const __nv_bfloat16* kb = &g_k[(size_t)bh * L_ * D_];

    #pragma unroll
    for (int it = 0; it < 4; it++) {
        int idx = tid + it * 128;              // 0..511
        int r = idx >> 3;                      // 8 uint4 per 64-elem row
        int c = (idx & 7) << 3;
        *reinterpret_cast<uint4*>(&qs[r][c]) =
            *reinterpret_cast<const uint4*>(&qb[(size_t)(m0 + r) * D_ + c]);
        *reinterpret_cast<uint4*>(&ks[r][c]) =
            *reinterpret_cast<const uint4*>(&kb[(size_t)(n0 + r) * D_ + c]);
    }
    __syncthreads();

    const int warp = tid >> 5;
    const int wr = warp >> 1;
    const int wc = warp & 1;

    wmma::fragment<wmma::accumulator, 16, 16, 16, float> acc[2][2];
    #pragma unroll
    for (int i = 0; i < 2; i++)
        #pragma unroll
        for (int j = 0; j < 2; j++)
            wmma::fill_fragment(acc[i][j], 0.0f);

    #pragma unroll
    for (int kk = 0; kk < D_; kk += 16) {
        wmma::fragment<wmma::matrix_a,16,16,16,__nv_bfloat16,wmma::row_major> af[2];
        wmma::fragment<wmma::matrix_b,16,16,16,__nv_bfloat16,wmma::col_major> bf[2];
        #pragma unroll
        for (int i = 0; i < 2; i++)
            wmma::load_matrix_sync(af[i], &qs[wr*32 + i*16][kk], 80);
        #pragma unroll
        for (int j = 0; j < 2; j++)
            wmma::load_matrix_sync(bf[j], &ks[wc*32 + j*16][kk], 80);
        #pragma unroll
        for (int i = 0; i < 2; i++)
            #pragma unroll
            for (int j = 0; j < 2; j++)
                wmma::mma_sync(acc[i][j], af[i], bf[j], acc[i][j]);
    }

    __syncthreads();   // done reading qs/ks; Es aliases them
    #pragma unroll
    for (int i = 0; i < 2; i++)
        #pragma unroll
        for (int j = 0; j < 2; j++)
            wmma::store_matrix_sync(&Es[wr*32 + i*16][wc*32 + j*16],
                                    acc[i][j], 68, wmma::mem_row_major);
    __syncthreads();

    const int* amb = am + b * L_;
    #pragma unroll
    for (int it = 0; it < 32; it++) {
        int idx = tid + it * 128;              // 0..4095
        int r = idx >> 6;
        int c = idx & 63;
        int m = m0 + r, n = n0 + c;
        float v = Es[r][c] * 0.125f;
        bool ok = (m <= n) && (amb[m] != 0) && (amb[n] != 0);
        obase[(size_t)m * L_ + n] = ok ? v : NEG;
    }
}

// ---------------------------------------------------------------------------
extern "C" void kernel_launch(void* const* d_in, const int* in_sizes, int n_in,
                              void* d_out, int out_size) {
    const float* inputs = (const float*)d_in[0];
    const float* W      = (const float*)d_in[1];
    const float* bias   = (const float*)d_in[2];
    const int*   am     = (const int*)d_in[3];
    float* out = (float*)d_out;

    prep_kernel<<<(NA2 + NW2 + NROPE + 255) / 256, 256>>>(inputs, W);
    gemm1_kernel<<<dim3(H_, MROWS / 128), 256>>>(bias);
    attn_kernel<<<dim3(L_ / 64, L_ / 64, BHN), 128>>>(am, out);
}

// round 4
// speedup vs baseline: 4.6184x; 1.0640x over previous
#include <cuda_runtime.h>
#include <cuda_bf16.h>
#include <mma.h>
#include <cstdint>

using namespace nvcuda;

#define B_    8
#define L_    512
#define H_    12
#define D_    64
#define HID   768
#define OUTD  1536
#define MROWS 4096          // B_*L_
#define BHN   96            // B_*H_

#define NA4   (MROWS * HID / 4)     // 786432 float4 units of A
#define NW4   (HID * OUTD / 4)      // 294912 float4 units of W
#define NROPE (L_ * 32)             //  16384

// Scratch (device globals — no runtime allocation allowed)
__device__ __nv_bfloat162 g_abf2[MROWS * HID / 2];
__device__ __nv_bfloat162 g_wbf2[HID * OUTD / 2];
__device__ __nv_bfloat16  g_q[BHN * L_ * D_];   // q, (bh, l, d) bf16
__device__ __nv_bfloat16  g_k[BHN * L_ * D_];   // k, (bh, l, d) bf16
__device__ float          g_sin[NROPE];
__device__ float          g_cos[NROPE];

static __device__ __forceinline__ void cp_async16(void* smem_dst, const void* gmem_src) {
    unsigned saddr = (unsigned)__cvta_generic_to_shared(smem_dst);
    asm volatile("cp.async.cg.shared.global [%0], [%1], 16;\n" :: "r"(saddr), "l"(gmem_src));
}
static __device__ __forceinline__ void cp_async_commit() {
    asm volatile("cp.async.commit_group;\n" ::: "memory");
}
static __device__ __forceinline__ void cp_async_wait1() {
    asm volatile("cp.async.wait_group 1;\n" ::: "memory");
}

// ---------------------------------------------------------------------------
// Kernel 0: convert inputs/W to bf16 (float4-wide) + build RoPE tables.
// ---------------------------------------------------------------------------
__global__ __launch_bounds__(256) void prep_kernel(const float* __restrict__ A,
                                                   const float* __restrict__ W) {
    int idx = blockIdx.x * 256 + threadIdx.x;
    if (idx < NA4) {
        float4 v = reinterpret_cast<const float4*>(A)[idx];
        __nv_bfloat162 lo = __floats2bfloat162_rn(v.x, v.y);
        __nv_bfloat162 hi = __floats2bfloat162_rn(v.z, v.w);
        reinterpret_cast<uint2*>(g_abf2)[idx] =
            make_uint2(*reinterpret_cast<unsigned*>(&lo), *reinterpret_cast<unsigned*>(&hi));
    } else if (idx < NA4 + NW4) {
        int j = idx - NA4;
        float4 v = reinterpret_cast<const float4*>(W)[j];
        __nv_bfloat162 lo = __floats2bfloat162_rn(v.x, v.y);
        __nv_bfloat162 hi = __floats2bfloat162_rn(v.z, v.w);
        reinterpret_cast<uint2*>(g_wbf2)[j] =
            make_uint2(*reinterpret_cast<unsigned*>(&lo), *reinterpret_cast<unsigned*>(&hi));
    } else if (idx < NA4 + NW4 + NROPE) {
        int t = idx - NA4 - NW4;
        int l = t >> 5;
        int i = t & 31;
        float invf = exp2f((float)i * -0.41524101186092027f);
        float s, c;
        sincosf((float)l * invf, &s, &c);
        g_sin[t] = s;
        g_cos[t] = c;
    }
}

// ---------------------------------------------------------------------------
// Kernel 1: x = inputs @ W (bf16 wmma), cp.async 2-stage pipeline (BK=32),
// fused bias + RoPE epilogue writing bf16 q/k in (bh,l,d) layout.
// Block tile 128x128 (one head's q|k columns), 8 warps (4x2).
// ---------------------------------------------------------------------------
#define G1_AS_STRIDE 40
#define G1_BS_STRIDE 136
#define G1_STAGE_BYTES (128*G1_AS_STRIDE*2 + 32*G1_BS_STRIDE*2)  // 10240+8704=18944

__global__ __launch_bounds__(256) void gemm1_kernel(const float* __restrict__ bias) {
    __shared__ __align__(16) unsigned char smem_raw[2 * G1_STAGE_BYTES];  // 37888

    const __nv_bfloat16* Abf = reinterpret_cast<const __nv_bfloat16*>(g_abf2);
    const __nv_bfloat16* Wbf = reinterpret_cast<const __nv_bfloat16*>(g_wbf2);

    const int h   = blockIdx.x;
    const int m0  = blockIdx.y * 128;
    const int n0  = h * 128;
    const int tid = threadIdx.x;
    const int warp = tid >> 5;
    const int wm = warp >> 1;            // 0..3
    const int wn = warp & 1;             // 0..1

    // A tile 128x32 bf16 = 512 uint4: r=idx>>2 (4 uint4/row), c=(idx&3)*8, idx in {tid, tid+256}
    // B tile 32x128 bf16 = 512 uint4: r=idx>>4 (16 uint4/row), c=(idx&15)*8
    auto copy_tile = [&](int kt, int stage) {
        unsigned char* base = smem_raw + stage * G1_STAGE_BYTES;
        __nv_bfloat16 (*As)[G1_AS_STRIDE] = reinterpret_cast<__nv_bfloat16 (*)[G1_AS_STRIDE]>(base);
        __nv_bfloat16 (*Bs)[G1_BS_STRIDE] = reinterpret_cast<__nv_bfloat16 (*)[G1_BS_STRIDE]>(base + 128*G1_AS_STRIDE*2);
        int k0 = kt * 32;
        #pragma unroll
        for (int it = 0; it < 2; it++) {
            int idx = tid + it * 256;          // 0..511
            int ar = idx >> 2;
            int ac = (idx & 3) << 3;
            cp_async16(&As[ar][ac], &Abf[(size_t)(m0 + ar) * HID + k0 + ac]);
            int br = idx >> 4;
            int bc = (idx & 15) << 3;
            cp_async16(&Bs[br][bc], &Wbf[(size_t)(k0 + br) * OUTD + n0 + bc]);
        }
    };

    wmma::fragment<wmma::accumulator, 16, 16, 16, float> acc[2][4];
    #pragma unroll
    for (int i = 0; i < 2; i++)
        #pragma unroll
        for (int j = 0; j < 4; j++)
            wmma::fill_fragment(acc[i][j], 0.0f);

    copy_tile(0, 0);
    cp_async_commit();

    const int NT = HID / 32;    // 24
    for (int kt = 0; kt < NT; kt++) {
        if (kt + 1 < NT) copy_tile(kt + 1, (kt + 1) & 1);
        cp_async_commit();
        cp_async_wait1();
        __syncthreads();

        unsigned char* base = smem_raw + (kt & 1) * G1_STAGE_BYTES;
        __nv_bfloat16 (*As)[G1_AS_STRIDE] = reinterpret_cast<__nv_bfloat16 (*)[G1_AS_STRIDE]>(base);
        __nv_bfloat16 (*Bs)[G1_BS_STRIDE] = reinterpret_cast<__nv_bfloat16 (*)[G1_BS_STRIDE]>(base + 128*G1_AS_STRIDE*2);

        #pragma unroll
        for (int kk = 0; kk < 32; kk += 16) {
            wmma::fragment<wmma::matrix_a,16,16,16,__nv_bfloat16,wmma::row_major> af[2];
            wmma::fragment<wmma::matrix_b,16,16,16,__nv_bfloat16,wmma::row_major> bf[4];
            #pragma unroll
            for (int i = 0; i < 2; i++)
                wmma::load_matrix_sync(af[i], &As[wm*32 + i*16][kk], G1_AS_STRIDE);
            #pragma unroll
            for (int j = 0; j < 4; j++)
                wmma::load_matrix_sync(bf[j], &Bs[kk][wn*64 + j*16], G1_BS_STRIDE);
            #pragma unroll
            for (int i = 0; i < 2; i++)
                #pragma unroll
                for (int j = 0; j < 4; j++)
                    wmma::mma_sync(acc[i][j], af[i], bf[j], acc[i][j]);
        }
        __syncthreads();
    }

    // Epilogue: two 64-row passes through Es (aliases smem), bias+RoPE, bf16 out.
    float (*Es)[132] = reinterpret_cast<float (*)[132]>(smem_raw);   // 64x132x4 = 33792 <= 37888
    #pragma unroll
    for (int half = 0; half < 2; half++) {
        __syncthreads();
        if ((wm >> 1) == half) {
            #pragma unroll
            for (int i = 0; i < 2; i++)
                #pragma unroll
                for (int j = 0; j < 4; j++)
                    wmma::store_matrix_sync(&Es[(wm & 1)*32 + i*16][wn*64 + j*16],
                                            acc[i][j], 132, wmma::mem_row_major);
        }
        __syncthreads();

        #pragma unroll
        for (int it = 0; it < 16; it++) {
            int idx = tid + it * 256;            // 0..4095
            int r   = idx >> 6;
            int col = (idx & 63) << 1;           // even col 0..126
            int m = m0 + half * 64 + r;
            int l = m & (L_ - 1);
            float x1 = Es[r][col]     + __ldg(&bias[n0 + col]);
            float x2 = Es[r][col + 1] + __ldg(&bias[n0 + col + 1]);
            int i = (col & 63) >> 1;
            float s = g_sin[l * 32 + i];
            float c = g_cos[l * 32 + i];
            float o1 = x1 * c - x2 * s;
            float o2 = x1 * s + x2 * c;
            int bh = (m >> 9) * H_ + h;
            __nv_bfloat16* dst = (col < 64) ? g_q : g_k;
            int d = col & 63;
            *reinterpret_cast<__nv_bfloat162*>(&dst[((size_t)bh * L_ + l) * D_ + d]) =
                __floats2bfloat162_rn(o1, o2);
        }
    }
}

// ---------------------------------------------------------------------------
// Kernel 2: logits[bh] = (q @ k^T) / 8, causal + padding mask. bf16 wmma.
// 128x128 output tiles, 256 threads (8 warps as 4x2).
// Tiles strictly below block diagonal write -FLT_MAX only.
// ---------------------------------------------------------------------------
__global__ __launch_bounds__(256) void attn_kernel(const int* __restrict__ am,
                                                   float* __restrict__ out) {
    const int bh = blockIdx.z;
    const int b  = bh / H_;
    const int tm = blockIdx.y, tn = blockIdx.x;
    const int m0 = tm * 128, n0 = tn * 128;
    float* obase = out + (size_t)bh * L_ * L_;
    const float NEG = __int_as_float(0xFF7FFFFF);  // -FLT_MAX == finfo(f32).min
    const int tid = threadIdx.x;

    if (tm > tn) {   // whole tile causally masked: 128x128 f32 = 4096 float4
        float4 negv = make_float4(NEG, NEG, NEG, NEG);
        #pragma unroll
        for (int it = 0; it < 16; it++) {
            int idx = tid + it * 256;          // 0..4095
            int r = idx >> 5;                  // 32 float4 per row
            int c = (idx & 31) << 2;
            *reinterpret_cast<float4*>(&obase[(size_t)(m0 + r) * L_ + n0 + c]) = negv;
        }
        return;
    }

    __shared__ __align__(16) unsigned char smem_raw[36864];
    __nv_bfloat16 (*qs)[72] = reinterpret_cast<__nv_bfloat16 (*)[72]>(smem_raw);            // 128x72x2 = 18432
    __nv_bfloat16 (*ks)[72] = reinterpret_cast<__nv_bfloat16 (*)[72]>(smem_raw + 18432);
    float (*Es)[132]        = reinterpret_cast<float (*)[132]>(smem_raw);                   // 64x132x4 = 33792

    const __nv_bfloat16* qb = &g_q[(size_t)bh * L_ * D_];
    const __nv_bfloat16* kb = &g_k[(size_t)bh * L_ * D_];

    // 128 rows x 64 cols bf16 = 1024 uint4 per matrix; 4 per thread each
    #pragma unroll
    for (int it = 0; it < 4; it++) {
        int idx = tid + it * 256;              // 0..1023
        int r = idx >> 3;                      // 8 uint4 per row
        int c = (idx & 7) << 3;
        *reinterpret_cast<uint4*>(&qs[r][c]) =
            *reinterpret_cast<const uint4*>(&qb[(size_t)(m0 + r) * D_ + c]);
        *reinterpret_cast<uint4*>(&ks[r][c]) =
            *reinterpret_cast<const uint4*>(&kb[(size_t)(n0 + r) * D_ + c]);
    }
    __syncthreads();

    const int warp = tid >> 5;
    const int wm = warp >> 1;    // 0..3
    const int wn = warp & 1;     // 0..1

    wmma::fragment<wmma::accumulator, 16, 16, 16, float> acc[2][4];
    #pragma unroll
    for (int i = 0; i < 2; i++)
        #pragma unroll
        for (int j = 0; j < 4; j++)
            wmma::fill_fragment(acc[i][j], 0.0f);

    #pragma unroll
    for (int kk = 0; kk < D_; kk += 16) {
        wmma::fragment<wmma::matrix_a,16,16,16,__nv_bfloat16,wmma::row_major> af[2];
        wmma::fragment<wmma::matrix_b,16,16,16,__nv_bfloat16,wmma::col_major> bf[4];
        #pragma unroll
        for (int i = 0; i < 2; i++)
            wmma::load_matrix_sync(af[i], &qs[wm*32 + i*16][kk], 72);
        #pragma unroll
        for (int j = 0; j < 4; j++)
            wmma::load_matrix_sync(bf[j], &ks[wn*64 + j*16][kk], 72);
        #pragma unroll
        for (int i = 0; i < 2; i++)
            #pragma unroll
            for (int j = 0; j < 4; j++)
                wmma::mma_sync(acc[i][j], af[i], bf[j], acc[i][j]);
    }

    const int* amb = am + b * L_;

    // Two 64-row passes: stage to Es (aliases qs/ks), masked float4 writes.
    #pragma unroll
    for (int half = 0; half < 2; half++) {
        __syncthreads();
        if ((wm >> 1) == half) {
            #pragma unroll
            for (int i = 0; i < 2; i++)
                #pragma unroll
                for (int j = 0; j < 4; j++)
                    wmma::store_matrix_sync(&Es[(wm & 1)*32 + i*16][wn*64 + j*16],
                                            acc[i][j], 132, wmma::mem_row_major);
        }
        __syncthreads();

        // 64 rows x 32 float4 = 2048 / 256 = 8 iterations
        #pragma unroll
        for (int it = 0; it < 8; it++) {
            int f = tid + it * 256;            // 0..2047
            int r = f >> 5;
            int c4 = (f & 31) << 2;
            int m = m0 + half * 64 + r;
            int n = n0 + c4;
            bool rowok = (amb[m] != 0);
            float4 v;
            float e0 = Es[r][c4+0] * 0.125f;
            float e1 = Es[r][c4+1] * 0.125f;
            float e2 = Es[r][c4+2] * 0.125f;
            float e3 = Es[r][c4+3] * 0.125f;
            v.x = (rowok && (m <= n+0) && (amb[n+0] != 0)) ? e0 : NEG;
            v.y = (rowok && (m <= n+1) && (amb[n+1] != 0)) ? e1 : NEG;
            v.z = (rowok && (m <= n+2) && (amb[n+2] != 0)) ? e2 : NEG;
            v.w = (rowok && (m <= n+3) && (amb[n+3] != 0)) ? e3 : NEG;
            *reinterpret_cast<float4*>(&obase[(size_t)m * L_ + n]) = v;
        }
    }
}

// ---------------------------------------------------------------------------
extern "C" void kernel_launch(void* const* d_in, const int* in_sizes, int n_in,
                              void* d_out, int out_size) {
    const float* inputs = (const float*)d_in[0];
    const float* W      = (const float*)d_in[1];
    const float* bias   = (const float*)d_in[2];
    const int*   am     = (const int*)d_in[3];
    float* out = (float*)d_out;

    prep_kernel<<<(NA4 + NW4 + NROPE + 255) / 256, 256>>>(inputs, W);
    gemm1_kernel<<<dim3(H_, MROWS / 128), 256>>>(bias);
    attn_kernel<<<dim3(L_ / 128, L_ / 128, BHN), 256>>>(am, out);
}

// round 5
// speedup vs baseline: 4.9310x; 1.0677x over previous
#include <cuda_runtime.h>
#include <cuda_bf16.h>
#include <mma.h>
#include <cstdint>

using namespace nvcuda;

#define B_    8
#define L_    512
#define H_    12
#define D_    64
#define HID   768
#define OUTD  1536
#define MROWS 4096          // B_*L_
#define BHN   96            // B_*H_

#define NA4   (MROWS * HID / 4)     // 786432 float4 units of A
#define NW4   (HID * OUTD / 4)      // 294912 float4 units of W
#define NCV4  (NA4 + NW4)           // 1081344
#define HALF4 (NCV4 / 2)            //  540672
#define NROPE (L_ * 32)             //   16384

// Scratch (device globals — no runtime allocation allowed)
__device__ __nv_bfloat162 g_abf2[MROWS * HID / 2];
__device__ __nv_bfloat162 g_wbf2[HID * OUTD / 2];
__device__ __nv_bfloat16  g_q[BHN * L_ * D_];   // q, (bh, l, d) bf16
__device__ __nv_bfloat16  g_k[BHN * L_ * D_];   // k, (bh, l, d) bf16
__device__ float          g_sin[NROPE];
__device__ float          g_cos[NROPE];

static __device__ __forceinline__ void cp_async16(void* smem_dst, const void* gmem_src) {
    unsigned saddr = (unsigned)__cvta_generic_to_shared(smem_dst);
    asm volatile("cp.async.cg.shared.global [%0], [%1], 16;\n" :: "r"(saddr), "l"(gmem_src));
}
static __device__ __forceinline__ void cp_async_commit() {
    asm volatile("cp.async.commit_group;\n" ::: "memory");
}
static __device__ __forceinline__ void cp_async_wait1() {
    asm volatile("cp.async.wait_group 1;\n" ::: "memory");
}

// ---------------------------------------------------------------------------
// Kernel 0: convert inputs/W to bf16 + RoPE tables. 2 float4 per thread (MLP).
// ---------------------------------------------------------------------------
static __device__ __forceinline__ void conv_one(const float* __restrict__ A,
                                                const float* __restrict__ W, int j) {
    if (j < NA4) {
        float4 v = reinterpret_cast<const float4*>(A)[j];
        __nv_bfloat162 lo = __floats2bfloat162_rn(v.x, v.y);
        __nv_bfloat162 hi = __floats2bfloat162_rn(v.z, v.w);
        reinterpret_cast<uint2*>(g_abf2)[j] =
            make_uint2(*reinterpret_cast<unsigned*>(&lo), *reinterpret_cast<unsigned*>(&hi));
    } else {
        int t = j - NA4;
        float4 v = reinterpret_cast<const float4*>(W)[t];
        __nv_bfloat162 lo = __floats2bfloat162_rn(v.x, v.y);
        __nv_bfloat162 hi = __floats2bfloat162_rn(v.z, v.w);
        reinterpret_cast<uint2*>(g_wbf2)[t] =
            make_uint2(*reinterpret_cast<unsigned*>(&lo), *reinterpret_cast<unsigned*>(&hi));
    }
}

__global__ __launch_bounds__(256) void prep_kernel(const float* __restrict__ A,
                                                   const float* __restrict__ W) {
    int idx = blockIdx.x * 256 + threadIdx.x;
    if (idx < HALF4) {
        conv_one(A, W, idx);
        conv_one(A, W, idx + HALF4);
    } else if (idx < HALF4 + NROPE) {
        int t = idx - HALF4;
        int l = t >> 5;
        int i = t & 31;
        float invf = exp2f((float)i * -0.41524101186092027f);
        float s, c;
        sincosf((float)l * invf, &s, &c);
        g_sin[t] = s;
        g_cos[t] = c;
    }
}

// ---------------------------------------------------------------------------
// Kernel 1: x = inputs @ W (bf16 wmma), cp.async 2-stage pipeline (BK=32),
// fused bias + RoPE epilogue writing bf16 q/k in (bh,l,d) layout.
// Block tile 128x128 (one head's q|k columns), 8 warps (4x2).
// ---------------------------------------------------------------------------
#define G1_AS_STRIDE 40
#define G1_BS_STRIDE 136
#define G1_STAGE_BYTES (128*G1_AS_STRIDE*2 + 32*G1_BS_STRIDE*2)  // 10240+8704=18944

__global__ __launch_bounds__(256) void gemm1_kernel(const float* __restrict__ bias) {
    __shared__ __align__(16) unsigned char smem_raw[2 * G1_STAGE_BYTES];  // 37888

    const __nv_bfloat16* Abf = reinterpret_cast<const __nv_bfloat16*>(g_abf2);
    const __nv_bfloat16* Wbf = reinterpret_cast<const __nv_bfloat16*>(g_wbf2);

    const int h   = blockIdx.x;
    const int m0  = blockIdx.y * 128;
    const int n0  = h * 128;
    const int tid = threadIdx.x;
    const int warp = tid >> 5;
    const int wm = warp >> 1;            // 0..3
    const int wn = warp & 1;             // 0..1

    auto copy_tile = [&](int kt, int stage) {
        unsigned char* base = smem_raw + stage * G1_STAGE_BYTES;
        __nv_bfloat16 (*As)[G1_AS_STRIDE] = reinterpret_cast<__nv_bfloat16 (*)[G1_AS_STRIDE]>(base);
        __nv_bfloat16 (*Bs)[G1_BS_STRIDE] = reinterpret_cast<__nv_bfloat16 (*)[G1_BS_STRIDE]>(base + 128*G1_AS_STRIDE*2);
        int k0 = kt * 32;
        #pragma unroll
        for (int it = 0; it < 2; it++) {
            int idx = tid + it * 256;          // 0..511
            int ar = idx >> 2;
            int ac = (idx & 3) << 3;
            cp_async16(&As[ar][ac], &Abf[(size_t)(m0 + ar) * HID + k0 + ac]);
            int br = idx >> 4;
            int bc = (idx & 15) << 3;
            cp_async16(&Bs[br][bc], &Wbf[(size_t)(k0 + br) * OUTD + n0 + bc]);
        }
    };

    wmma::fragment<wmma::accumulator, 16, 16, 16, float> acc[2][4];
    #pragma unroll
    for (int i = 0; i < 2; i++)
        #pragma unroll
        for (int j = 0; j < 4; j++)
            wmma::fill_fragment(acc[i][j], 0.0f);

    copy_tile(0, 0);
    cp_async_commit();

    const int NT = HID / 32;    // 24
    for (int kt = 0; kt < NT; kt++) {
        if (kt + 1 < NT) copy_tile(kt + 1, (kt + 1) & 1);
        cp_async_commit();
        cp_async_wait1();
        __syncthreads();

        unsigned char* base = smem_raw + (kt & 1) * G1_STAGE_BYTES;
        __nv_bfloat16 (*As)[G1_AS_STRIDE] = reinterpret_cast<__nv_bfloat16 (*)[G1_AS_STRIDE]>(base);
        __nv_bfloat16 (*Bs)[G1_BS_STRIDE] = reinterpret_cast<__nv_bfloat16 (*)[G1_BS_STRIDE]>(base + 128*G1_AS_STRIDE*2);

        #pragma unroll
        for (int kk = 0; kk < 32; kk += 16) {
            wmma::fragment<wmma::matrix_a,16,16,16,__nv_bfloat16,wmma::row_major> af[2];
            wmma::fragment<wmma::matrix_b,16,16,16,__nv_bfloat16,wmma::row_major> bf[4];
            #pragma unroll
            for (int i = 0; i < 2; i++)
                wmma::load_matrix_sync(af[i], &As[wm*32 + i*16][kk], G1_AS_STRIDE);
            #pragma unroll
            for (int j = 0; j < 4; j++)
                wmma::load_matrix_sync(bf[j], &Bs[kk][wn*64 + j*16], G1_BS_STRIDE);
            #pragma unroll
            for (int i = 0; i < 2; i++)
                #pragma unroll
                for (int j = 0; j < 4; j++)
                    wmma::mma_sync(acc[i][j], af[i], bf[j], acc[i][j]);
        }
        __syncthreads();
    }

    // Epilogue: two 64-row passes through Es (aliases smem), bias+RoPE, bf16 out.
    float (*Es)[132] = reinterpret_cast<float (*)[132]>(smem_raw);   // 64x132x4 = 33792 <= 37888
    const int colT = (tid & 63) << 1;           // fixed per thread
    const int iT   = (colT & 63) >> 1;          // fixed pair index within q or k
    const float b1 = __ldg(&bias[n0 + colT]);
    const float b2 = __ldg(&bias[n0 + colT + 1]);

    #pragma unroll
    for (int half = 0; half < 2; half++) {
        __syncthreads();
        if ((wm >> 1) == half) {
            #pragma unroll
            for (int i = 0; i < 2; i++)
                #pragma unroll
                for (int j = 0; j < 4; j++)
                    wmma::store_matrix_sync(&Es[(wm & 1)*32 + i*16][wn*64 + j*16],
                                            acc[i][j], 132, wmma::mem_row_major);
        }
        __syncthreads();

        #pragma unroll
        for (int it = 0; it < 16; it++) {
            int idx = tid + it * 256;            // 0..4095
            int r   = idx >> 6;
            int m = m0 + half * 64 + r;
            int l = m & (L_ - 1);
            float x1 = Es[r][colT]     + b1;
            float x2 = Es[r][colT + 1] + b2;
            float s = g_sin[l * 32 + iT];
            float c = g_cos[l * 32 + iT];
            float o1 = x1 * c - x2 * s;
            float o2 = x1 * s + x2 * c;
            int bh = (m >> 9) * H_ + h;
            __nv_bfloat16* dst = (colT < 64) ? g_q : g_k;
            int d = colT & 63;
            *reinterpret_cast<__nv_bfloat162*>(&dst[((size_t)bh * L_ + l) * D_ + d]) =
                __floats2bfloat162_rn(o1, o2);
        }
    }
}

// ---------------------------------------------------------------------------
// Kernel 2: logits[bh] = (q @ k^T) / 8, causal + padding mask. bf16 wmma.
// 128x128 output tiles, 256 threads (8 warps as 4x2).
// Mask flags staged in smem (no per-element global mask loads).
// ---------------------------------------------------------------------------
__global__ __launch_bounds__(256) void attn_kernel(const int* __restrict__ am,
                                                   float* __restrict__ out) {
    const int bh = blockIdx.z;
    const int b  = bh / H_;
    const int tm = blockIdx.y, tn = blockIdx.x;
    const int m0 = tm * 128, n0 = tn * 128;
    float* obase = out + (size_t)bh * L_ * L_;
    const float NEG = __int_as_float(0xFF7FFFFF);  // -FLT_MAX == finfo(f32).min
    const int tid = threadIdx.x;

    if (tm > tn) {   // whole tile causally masked: 128x128 f32 = 4096 float4
        float4 negv = make_float4(NEG, NEG, NEG, NEG);
        #pragma unroll
        for (int it = 0; it < 16; it++) {
            int idx = tid + it * 256;          // 0..4095
            int r = idx >> 5;                  // 32 float4 per row
            int c = (idx & 31) << 2;
            *reinterpret_cast<float4*>(&obase[(size_t)(m0 + r) * L_ + n0 + c]) = negv;
        }
        return;
    }

    __shared__ __align__(16) unsigned char smem_raw[36864];
    __shared__ unsigned char rowv[128];
    __shared__ unsigned char colv[128];
    __nv_bfloat16 (*qs)[72] = reinterpret_cast<__nv_bfloat16 (*)[72]>(smem_raw);            // 128x72x2 = 18432
    __nv_bfloat16 (*ks)[72] = reinterpret_cast<__nv_bfloat16 (*)[72]>(smem_raw + 18432);
    float (*Es)[132]        = reinterpret_cast<float (*)[132]>(smem_raw);                   // 64x132x4 = 33792

    const int* amb = am + b * L_;
    if (tid < 128)       rowv[tid]       = (unsigned char)(amb[m0 + tid] != 0);
    else                 colv[tid - 128] = (unsigned char)(amb[n0 + tid - 128] != 0);

    const __nv_bfloat16* qb = &g_q[(size_t)bh * L_ * D_];
    const __nv_bfloat16* kb = &g_k[(size_t)bh * L_ * D_];

    // 128 rows x 64 cols bf16 = 1024 uint4 per matrix; 4 per thread each
    #pragma unroll
    for (int it = 0; it < 4; it++) {
        int idx = tid + it * 256;              // 0..1023
        int r = idx >> 3;                      // 8 uint4 per row
        int c = (idx & 7) << 3;
        *reinterpret_cast<uint4*>(&qs[r][c]) =
            *reinterpret_cast<const uint4*>(&qb[(size_t)(m0 + r) * D_ + c]);
        *reinterpret_cast<uint4*>(&ks[r][c]) =
            *reinterpret_cast<const uint4*>(&kb[(size_t)(n0 + r) * D_ + c]);
    }
    __syncthreads();

    const int warp = tid >> 5;
    const int wm = warp >> 1;    // 0..3
    const int wn = warp & 1;     // 0..1

    wmma::fragment<wmma::accumulator, 16, 16, 16, float> acc[2][4];
    #pragma unroll
    for (int i = 0; i < 2; i++)
        #pragma unroll
        for (int j = 0; j < 4; j++)
            wmma::fill_fragment(acc[i][j], 0.0f);

    #pragma unroll
    for (int kk = 0; kk < D_; kk += 16) {
        wmma::fragment<wmma::matrix_a,16,16,16,__nv_bfloat16,wmma::row_major> af[2];
        wmma::fragment<wmma::matrix_b,16,16,16,__nv_bfloat16,wmma::col_major> bf[4];
        #pragma unroll
        for (int i = 0; i < 2; i++)
            wmma::load_matrix_sync(af[i], &qs[wm*32 + i*16][kk], 72);
        #pragma unroll
        for (int j = 0; j < 4; j++)
            wmma::load_matrix_sync(bf[j], &ks[wn*64 + j*16][kk], 72);
        #pragma unroll
        for (int i = 0; i < 2; i++)
            #pragma unroll
            for (int j = 0; j < 4; j++)
                wmma::mma_sync(acc[i][j], af[i], bf[j], acc[i][j]);
    }

    // Two 64-row passes: stage to Es (aliases qs/ks), masked float4 writes.
    #pragma unroll
    for (int half = 0; half < 2; half++) {
        __syncthreads();
        if ((wm >> 1) == half) {
            #pragma unroll
            for (int i = 0; i < 2; i++)
                #pragma unroll
                for (int j = 0; j < 4; j++)
                    wmma::store_matrix_sync(&Es[(wm & 1)*32 + i*16][wn*64 + j*16],
                                            acc[i][j], 132, wmma::mem_row_major);
        }
        __syncthreads();

        // 64 rows x 32 float4 = 2048 / 256 = 8 iterations
        #pragma unroll
        for (int it = 0; it < 8; it++) {
            int f = tid + it * 256;            // 0..2047
            int r = f >> 5;
            int c4 = (f & 31) << 2;
            int m = m0 + half * 64 + r;
            int n = n0 + c4;
            bool rowok = (rowv[half * 64 + r] != 0);
            uchar4 cv = *reinterpret_cast<const uchar4*>(&colv[c4]);
            float4 v;
            float e0 = Es[r][c4+0] * 0.125f;
            float e1 = Es[r][c4+1] * 0.125f;
            float e2 = Es[r][c4+2] * 0.125f;
            float e3 = Es[r][c4+3] * 0.125f;
            v.x = (rowok && cv.x && (m <= n+0)) ? e0 : NEG;
            v.y = (rowok && cv.y && (m <= n+1)) ? e1 : NEG;
            v.z = (rowok && cv.z && (m <= n+2)) ? e2 : NEG;
            v.w = (rowok && cv.w && (m <= n+3)) ? e3 : NEG;
            *reinterpret_cast<float4*>(&obase[(size_t)m * L_ + n]) = v;
        }
    }
}

// ---------------------------------------------------------------------------
extern "C" void kernel_launch(void* const* d_in, const int* in_sizes, int n_in,
                              void* d_out, int out_size) {
    const float* inputs = (const float*)d_in[0];
    const float* W      = (const float*)d_in[1];
    const float* bias   = (const float*)d_in[2];
    const int*   am     = (const int*)d_in[3];
    float* out = (float*)d_out;

    prep_kernel<<<(HALF4 + NROPE + 255) / 256, 256>>>(inputs, W);
    gemm1_kernel<<<dim3(H_, MROWS / 128), 256>>>(bias);
    attn_kernel<<<dim3(L_ / 128, L_ / 128, BHN), 256>>>(am, out);
}